// round 13
// baseline (speedup 1.0000x reference)
#include <cuda_runtime.h>
#include <cuda_fp16.h>
#include <cstddef>
#include <cstdint>

// Problem constants
#define BATCH 4
#define SEQ   2048
#define CDIM  1024
#define NHEAD 16
#define HDIM  64
#define BT    (BATCH*SEQ)       // 8192
#define QKV_N (3*CDIM)          // 3072

// Scratch (device globals; no allocation allowed)
__device__ alignas(16) __half g_q[BATCH*NHEAD*SEQ*HDIM];       // fp16
__device__ alignas(16) __half g_k[BATCH*NHEAD*SEQ*HDIM];
__device__ alignas(16) __half g_v[BATCH*NHEAD*SEQ*HDIM];
__device__ alignas(16) __half g_xh[BT*CDIM];                   // x fp16 [M,K]
__device__ alignas(16) __half g_yh[BT*CDIM];                   // y fp16 [M,K]
__device__ alignas(16) __half g_wah[CDIM*QKV_N];               // w_attn fp16 [K,N]
__device__ alignas(16) __half g_wph[CDIM*CDIM];                // w_proj fp16 [K,N]

// ---------------------------------------------------------------------------
// Helpers
// ---------------------------------------------------------------------------
__device__ __forceinline__ uint32_t smem_u32(const void* p) {
    return (uint32_t)__cvta_generic_to_shared(p);
}
__device__ __forceinline__ void mma16816(float* c, const uint32_t* a,
                                         uint32_t b0, uint32_t b1) {
    asm volatile(
        "mma.sync.aligned.m16n8k16.row.col.f32.f16.f16.f32 "
        "{%0,%1,%2,%3},{%4,%5,%6,%7},{%8,%9},{%0,%1,%2,%3};"
        : "+f"(c[0]), "+f"(c[1]), "+f"(c[2]), "+f"(c[3])
        : "r"(a[0]), "r"(a[1]), "r"(a[2]), "r"(a[3]), "r"(b0), "r"(b1));
}
__device__ __forceinline__ void ldmx4(uint32_t* r, uint32_t addr) {
    asm volatile("ldmatrix.sync.aligned.m8n8.x4.shared.b16 {%0,%1,%2,%3},[%4];"
                 : "=r"(r[0]), "=r"(r[1]), "=r"(r[2]), "=r"(r[3]) : "r"(addr));
}
__device__ __forceinline__ void ldmx2(uint32_t& r0, uint32_t& r1, uint32_t addr) {
    asm volatile("ldmatrix.sync.aligned.m8n8.x2.shared.b16 {%0,%1},[%2];"
                 : "=r"(r0), "=r"(r1) : "r"(addr));
}
__device__ __forceinline__ void ldmx2t(uint32_t& r0, uint32_t& r1, uint32_t addr) {
    asm volatile("ldmatrix.sync.aligned.m8n8.x2.trans.shared.b16 {%0,%1},[%2];"
                 : "=r"(r0), "=r"(r1) : "r"(addr));
}
__device__ __forceinline__ void cp16(uint32_t saddr, const void* g) {
    asm volatile("cp.async.cg.shared.global [%0], [%1], 16;" :: "r"(saddr), "l"(g));
}
__device__ __forceinline__ void cp_commit() { asm volatile("cp.async.commit_group;"); }
template<int Np> __device__ __forceinline__ void cp_wait() {
    asm volatile("cp.async.wait_group %0;" :: "n"(Np));
}

// ---------------------------------------------------------------------------
// Prep: fused fp32 -> fp16 conversion of x, w_attn, w_proj (one launch)
// ---------------------------------------------------------------------------
#define N4_X  (BT*CDIM/4)
#define N4_WA (CDIM*QKV_N/4)
#define N4_WP (CDIM*CDIM/4)
#define N4_TOT (N4_X + N4_WA + N4_WP)

__global__ __launch_bounds__(256) void conv_all(
    const float4* __restrict__ x, const float4* __restrict__ wa,
    const float4* __restrict__ wp,
    __half2* __restrict__ xh, __half2* __restrict__ wah,
    __half2* __restrict__ wph)
{
    int i = blockIdx.x * 256 + threadIdx.x;
    if (i >= N4_TOT) return;
    const float4* src;
    __half2* dst;
    int j;
    if (i < N4_X)               { src = x;  dst = xh;  j = i; }
    else if (i < N4_X + N4_WA)  { src = wa; dst = wah; j = i - N4_X; }
    else                        { src = wp; dst = wph; j = i - N4_X - N4_WA; }
    float4 v = src[j];
    dst[j * 2]     = __floats2half2_rn(v.x, v.y);
    dst[j * 2 + 1] = __floats2half2_rn(v.z, v.w);
}

// ---------------------------------------------------------------------------
// fp16 GEMM: C[M,N] = A[M,K] @ B[K,N], BK=64, double-buffered cp.async.
// 128x128 tile, 8 warps (warp tile 64x32), XOR-swizzled smem.
// EPI=0: fp32 C. EPI=1: QKV scatter as fp16 q/k/v.
// ---------------------------------------------------------------------------
#define SB_BYTES 32768u   // Ah(16K) | Bh(16K)
#define GEMM_SMEM (2 * SB_BYTES)

template<int EPI>
__global__ __launch_bounds__(256)
void gemm_f16(const __half* __restrict__ Ah, const __half* __restrict__ Bh,
              float* __restrict__ C, int N, int K)
{
    extern __shared__ char smem[];
    const uint32_t sbase = smem_u32(smem);

    const int t = threadIdx.x, lane = t & 31, w = t >> 5;
    const int m0 = blockIdx.y * 128, n0 = blockIdx.x * 128;
    const int wm = w & 1, wn = w >> 1;

    float acc[4][4][4] = {};
    const int NIT = K / 64;   // 16

    auto load_stage = [&](int it, int buf) {
        uint32_t sb = sbase + buf * SB_BYTES;
        int k0 = it * 64;
        // A: 128 rows x 8 chunks (128B/row), 4 chunks/thread
        #pragma unroll
        for (int u = 0; u < 4; ++u) {
            int q = t + u * 256;
            int r = q >> 3, c16 = q & 7;
            uint32_t sc = (uint32_t)(r * 8 + (c16 ^ (r & 7))) * 16;
            cp16(sb + sc, Ah + (size_t)(m0 + r) * K + k0 + c16 * 8);
        }
        // B: 64 rows x 16 chunks (256B/row), 4 chunks/thread
        #pragma unroll
        for (int u = 0; u < 4; ++u) {
            int q = t + u * 256;
            int k = q >> 4, c = q & 15;
            uint32_t sc = (uint32_t)(k * 16 + (c ^ (k & 7))) * 16;
            cp16(sb + 16384 + sc, Bh + (size_t)(k0 + k) * N + n0 + c * 8);
        }
    };

    load_stage(0, 0);
    cp_commit();

    for (int it = 0; it < NIT; ++it) {
        if (it + 1 < NIT) {
            load_stage(it + 1, (it + 1) & 1);
            cp_commit();
            cp_wait<1>();
        } else {
            cp_wait<0>();
        }
        __syncthreads();

        uint32_t sb  = sbase + (it & 1) * SB_BYTES;
        uint32_t sAh = sb, sBh = sb + 16384;

        #pragma unroll
        for (int kk = 0; kk < 4; ++kk) {
            uint32_t ar[4][4], bf[4][2];
            #pragma unroll
            for (int mt = 0; mt < 4; ++mt) {
                int r = wm * 64 + mt * 16 + (lane & 15);
                int c16 = kk * 2 + (lane >> 4);
                uint32_t off = (uint32_t)(r * 8 + (c16 ^ (r & 7))) * 16;
                ldmx4(ar[mt], sAh + off);
            }
            #pragma unroll
            for (int nt = 0; nt < 4; ++nt) {
                int k = kk * 16 + (lane & 15);
                int c = wn * 4 + nt;
                uint32_t off = (uint32_t)(k * 16 + (c ^ (k & 7))) * 16;
                ldmx2t(bf[nt][0], bf[nt][1], sBh + off);
            }
            #pragma unroll
            for (int mt = 0; mt < 4; ++mt)
                #pragma unroll
                for (int nt = 0; nt < 4; ++nt)
                    mma16816(acc[mt][nt], ar[mt], bf[nt][0], bf[nt][1]);
        }
        __syncthreads();
    }

    // epilogue
    int g = lane >> 2, qoff = (lane & 3) * 2;
    if (EPI == 0) {
        #pragma unroll
        for (int mt = 0; mt < 4; ++mt) {
            int r0 = m0 + wm * 64 + mt * 16 + g;
            #pragma unroll
            for (int nt = 0; nt < 4; ++nt) {
                int n = n0 + wn * 32 + nt * 8 + qoff;
                *(float2*)(C + (size_t)r0 * N + n) =
                    make_float2(acc[mt][nt][0], acc[mt][nt][1]);
                *(float2*)(C + (size_t)(r0 + 8) * N + n) =
                    make_float2(acc[mt][nt][2], acc[mt][nt][3]);
            }
        }
    } else {
        int n_first = n0 + wn * 32;
        int region = n_first >> 10;
        int h = (n_first & 1023) >> 6;
        int dbase = n_first & 63;                 // 0 or 32
        __half* dst = (region == 0) ? g_q : (region == 1) ? g_k : g_v;
        #pragma unroll
        for (int mt = 0; mt < 4; ++mt) {
            int r = m0 + wm * 64 + mt * 16 + g;
            int b = r >> 11, tt = r & 2047;
            size_t base = ((size_t)(b * NHEAD + h) * SEQ + tt) * HDIM;
            #pragma unroll
            for (int nt = 0; nt < 4; ++nt) {
                int d = dbase + nt * 8 + qoff;
                *(__half2*)(dst + base + d) =
                    __floats2half2_rn(acc[mt][nt][0], acc[mt][nt][1]);
                *(__half2*)(dst + base + 8 * HDIM + d) =
                    __floats2half2_rn(acc[mt][nt][2], acc[mt][nt][3]);
            }
        }
    }
}

// ---------------------------------------------------------------------------
// Flash attention, single-pass fp16 (round-11 proven version).
// Double-buffered cp.async K/V tiles, heavy CTAs first. Writes y as fp16.
// ---------------------------------------------------------------------------
#define LDK 72                  // padded smem row (fp16 elems)
#define ABUF 9216               // bytes per 64xLDK fp16 array
#define KVTILE (2*ABUF)         // kh | vh

__global__ __launch_bounds__(256) void flash_attn_mma()
{
    __shared__ char sm[2 * KVTILE];       // 36,864 B (Q staged here first)
    const uint32_t smb = smem_u32(sm);

    int t = threadIdx.x, lane = t & 31, w = t >> 5;
    int bx = (gridDim.x - 1) - blockIdx.x;        // heavy blocks first
    int bh2 = blockIdx.y;
    int b = bh2 >> 4, h = bh2 & 15;

    size_t headoff = (size_t)bh2 * SEQ * HDIM;

    // ---- stage Q tile (128x64)
    {
        const __half* qg = g_q + headoff + (size_t)bx * 128 * HDIM;
        #pragma unroll
        for (int i = 0; i < 4; ++i) {
            int q = t + i * 256;
            int r = q >> 3, c8 = q & 7;
            uint32_t soff = (uint32_t)(r * LDK + c8 * 8) * 2;
            cp16(smb + soff, qg + r * 64 + c8 * 8);
        }
    }
    cp_commit();
    cp_wait<0>();
    __syncthreads();

    uint32_t qf[4][4];
    {
        int row = w * 16 + (lane & 15);
        #pragma unroll
        for (int kt = 0; kt < 4; ++kt) {
            int col = kt * 16 + (lane >> 4) * 8;
            ldmx4(qf[kt], smb + (uint32_t)(row * LDK + col) * 2);
        }
    }
    __syncthreads();

    float oacc[8][4];
    #pragma unroll
    for (int i = 0; i < 8; ++i) { oacc[i][0]=0.f; oacc[i][1]=0.f; oacc[i][2]=0.f; oacc[i][3]=0.f; }

    float m0 = -1e30f, m1 = -1e30f, l0 = 0.f, l1 = 0.f;
    int g    = lane >> 2;
    int qoff = (lane & 3) * 2;
    int rw   = bx * 128 + w * 16;
    const float scale = 0.125f;

    auto load_kv = [&](int kt, int buf) {
        size_t tb = headoff + (size_t)kt * 64 * HDIM;
        uint32_t bb = smb + buf * KVTILE;
        #pragma unroll
        for (int i = 0; i < 2; ++i) {
            int q = t + i * 256;
            int r = q >> 3, c8 = q & 7;
            uint32_t soff = (uint32_t)(r * LDK + c8 * 8) * 2;
            size_t go = tb + r * 64 + c8 * 8;
            cp16(bb + soff,        g_k + go);
            cp16(bb + ABUF + soff, g_v + go);
        }
    };

    int ntiles = 2 * bx + 2;
    load_kv(0, 0);
    cp_commit();

    for (int kt = 0; kt < ntiles; ++kt) {
        if (kt + 1 < ntiles) {
            load_kv(kt + 1, (kt + 1) & 1);
            cp_commit();
            cp_wait<1>();
        } else {
            cp_wait<0>();
        }
        __syncthreads();

        uint32_t bb = smb + (kt & 1) * KVTILE;

        if (kt * 64 <= rw + 15) {
            // ---- S = Q K^T
            float sacc[8][4];
            #pragma unroll
            for (int i = 0; i < 8; ++i) { sacc[i][0]=0.f; sacc[i][1]=0.f; sacc[i][2]=0.f; sacc[i][3]=0.f; }

            #pragma unroll
            for (int c = 0; c < 4; ++c) {
                int col = c * 16 + (((lane & 15) >> 3)) * 8;
                int keyrb = lane & 7;
                uint32_t kf[8][2];
                #pragma unroll
                for (int nt = 0; nt < 8; ++nt)
                    ldmx2(kf[nt][0], kf[nt][1],
                          bb + (uint32_t)((nt * 8 + keyrb) * LDK + col) * 2);
                #pragma unroll
                for (int nt = 0; nt < 8; ++nt)
                    mma16816(sacc[nt], qf[c], kf[nt][0], kf[nt][1]);
            }

            // ---- scale + causal mask + row max
            int i0 = rw + g, i1 = rw + g + 8;
            float mt0 = -1e30f, mt1 = -1e30f;
            #pragma unroll
            for (int nt = 0; nt < 8; ++nt) {
                int j0 = kt * 64 + nt * 8 + qoff;
                float s0 = sacc[nt][0] * scale;
                float s1 = sacc[nt][1] * scale;
                float s2 = sacc[nt][2] * scale;
                float s3 = sacc[nt][3] * scale;
                if (j0     > i0) s0 = -1e30f;
                if (j0 + 1 > i0) s1 = -1e30f;
                if (j0     > i1) s2 = -1e30f;
                if (j0 + 1 > i1) s3 = -1e30f;
                sacc[nt][0] = s0; sacc[nt][1] = s1;
                sacc[nt][2] = s2; sacc[nt][3] = s3;
                mt0 = fmaxf(mt0, fmaxf(s0, s1));
                mt1 = fmaxf(mt1, fmaxf(s2, s3));
            }
            mt0 = fmaxf(mt0, __shfl_xor_sync(0xffffffffu, mt0, 1));
            mt0 = fmaxf(mt0, __shfl_xor_sync(0xffffffffu, mt0, 2));
            mt1 = fmaxf(mt1, __shfl_xor_sync(0xffffffffu, mt1, 1));
            mt1 = fmaxf(mt1, __shfl_xor_sync(0xffffffffu, mt1, 2));

            float mn0 = fmaxf(m0, mt0), mn1 = fmaxf(m1, mt1);
            float a0 = __expf(m0 - mn0), a1 = __expf(m1 - mn1);
            m0 = mn0; m1 = mn1;
            l0 *= a0;  l1 *= a1;
            #pragma unroll
            for (int nt = 0; nt < 8; ++nt) {
                oacc[nt][0] *= a0; oacc[nt][1] *= a0;
                oacc[nt][2] *= a1; oacc[nt][3] *= a1;
            }

            // ---- P = exp(S - m), O += P V
            #pragma unroll
            for (int c2 = 0; c2 < 4; ++c2) {
                float p0 = __expf(sacc[2*c2  ][0] - m0);
                float p1 = __expf(sacc[2*c2  ][1] - m0);
                float p2 = __expf(sacc[2*c2  ][2] - m1);
                float p3 = __expf(sacc[2*c2  ][3] - m1);
                float p4 = __expf(sacc[2*c2+1][0] - m0);
                float p5 = __expf(sacc[2*c2+1][1] - m0);
                float p6 = __expf(sacc[2*c2+1][2] - m1);
                float p7 = __expf(sacc[2*c2+1][3] - m1);
                l0 += p0 + p1 + p4 + p5;
                l1 += p2 + p3 + p6 + p7;

                uint32_t pr[4];
                {
                    __half2 hp;
                    hp = __floats2half2_rn(p0, p1); pr[0] = *(uint32_t*)&hp;
                    hp = __floats2half2_rn(p2, p3); pr[1] = *(uint32_t*)&hp;
                    hp = __floats2half2_rn(p4, p5); pr[2] = *(uint32_t*)&hp;
                    hp = __floats2half2_rn(p6, p7); pr[3] = *(uint32_t*)&hp;
                }

                int keyr = c2 * 16 + (lane & 15);
                uint32_t vf[8][2];
                #pragma unroll
                for (int nt = 0; nt < 8; ++nt)
                    ldmx2t(vf[nt][0], vf[nt][1],
                           bb + ABUF + (uint32_t)(keyr * LDK + nt * 8) * 2);
                #pragma unroll
                for (int nt = 0; nt < 8; ++nt)
                    mma16816(oacc[nt], pr, vf[nt][0], vf[nt][1]);
            }
        }
        __syncthreads();
    }

    // ---- finalize: write y as fp16
    l0 += __shfl_xor_sync(0xffffffffu, l0, 1);
    l0 += __shfl_xor_sync(0xffffffffu, l0, 2);
    l1 += __shfl_xor_sync(0xffffffffu, l1, 1);
    l1 += __shfl_xor_sync(0xffffffffu, l1, 2);
    float inv0 = 1.f / l0, inv1 = 1.f / l1;

    size_t o0 = ((size_t)(b * SEQ + rw + g    )) * CDIM + h * 64;
    size_t o1 = ((size_t)(b * SEQ + rw + g + 8)) * CDIM + h * 64;
    #pragma unroll
    for (int nt = 0; nt < 8; ++nt) {
        *(__half2*)(g_yh + o0 + nt * 8 + qoff) =
            __floats2half2_rn(oacc[nt][0] * inv0, oacc[nt][1] * inv0);
        *(__half2*)(g_yh + o1 + nt * 8 + qoff) =
            __floats2half2_rn(oacc[nt][2] * inv1, oacc[nt][3] * inv1);
    }
}

// ---------------------------------------------------------------------------
// Launch: fused prep -> QKV GEMM -> attention -> proj GEMM
// ---------------------------------------------------------------------------
extern "C" void kernel_launch(void* const* d_in, const int* in_sizes, int n_in,
                              void* d_out, int out_size)
{
    const float* x      = (const float*)d_in[0];
    const float* w_attn = (const float*)d_in[1];
    const float* w_proj = (const float*)d_in[2];
    float* out = (float*)d_out;

    __half *xh, *yh, *wah, *wph;
    cudaGetSymbolAddress((void**)&xh,  g_xh);
    cudaGetSymbolAddress((void**)&yh,  g_yh);
    cudaGetSymbolAddress((void**)&wah, g_wah);
    cudaGetSymbolAddress((void**)&wph, g_wph);

    cudaFuncSetAttribute((const void*)gemm_f16<0>,
                         cudaFuncAttributeMaxDynamicSharedMemorySize, GEMM_SMEM);
    cudaFuncSetAttribute((const void*)gemm_f16<1>,
                         cudaFuncAttributeMaxDynamicSharedMemorySize, GEMM_SMEM);

    // fused fp16 conversion (x, w_attn, w_proj in one launch)
    conv_all<<<(N4_TOT + 255) / 256, 256>>>(
        (const float4*)x, (const float4*)w_attn, (const float4*)w_proj,
        (__half2*)xh, (__half2*)wah, (__half2*)wph);

    // 1) QKV GEMM: [8192,1024]@[1024,3072] -> fp16 q/k/v
    {
        dim3 grid(QKV_N / 128, BT / 128);   // 24 x 64
        gemm_f16<1><<<grid, 256, GEMM_SMEM>>>(xh, wah, nullptr, QKV_N, CDIM);
    }
    // 2) attention (single-pass fp16, heavy CTAs first)
    {
        dim3 grid(SEQ / 128, BATCH * NHEAD);  // 16 x 64
        flash_attn_mma<<<grid, 256>>>();
    }
    // 3) proj GEMM: [8192,1024]@[1024,1024] -> fp32 out
    {
        dim3 grid(CDIM / 128, BT / 128);    // 8 x 64
        gemm_f16<0><<<grid, 256, GEMM_SMEM>>>(yh, wph, out, CDIM, CDIM);
    }
}

// round 14
// speedup vs baseline: 1.0641x; 1.0641x over previous
#include <cuda_runtime.h>
#include <cuda_fp16.h>
#include <cstddef>
#include <cstdint>

// Problem constants
#define BATCH 4
#define SEQ   2048
#define CDIM  1024
#define NHEAD 16
#define HDIM  64
#define BT    (BATCH*SEQ)       // 8192
#define QKV_N (3*CDIM)          // 3072

// Scratch (device globals; no allocation allowed)
__device__ alignas(16) __half g_q[BATCH*NHEAD*SEQ*HDIM];       // fp16
__device__ alignas(16) __half g_k[BATCH*NHEAD*SEQ*HDIM];
__device__ alignas(16) __half g_v[BATCH*NHEAD*SEQ*HDIM];
__device__ alignas(16) __half g_xh[BT*CDIM];                   // x fp16 [M,K]
__device__ alignas(16) __half g_yh[BT*CDIM];                   // y fp16 [M,K]
__device__ alignas(16) __half g_wah[CDIM*QKV_N];               // w_attn fp16 [K,N]
__device__ alignas(16) __half g_wph[CDIM*CDIM];                // w_proj fp16 [K,N]

// ---------------------------------------------------------------------------
// Helpers
// ---------------------------------------------------------------------------
__device__ __forceinline__ uint32_t smem_u32(const void* p) {
    return (uint32_t)__cvta_generic_to_shared(p);
}
__device__ __forceinline__ void mma16816(float* c, const uint32_t* a,
                                         uint32_t b0, uint32_t b1) {
    asm volatile(
        "mma.sync.aligned.m16n8k16.row.col.f32.f16.f16.f32 "
        "{%0,%1,%2,%3},{%4,%5,%6,%7},{%8,%9},{%0,%1,%2,%3};"
        : "+f"(c[0]), "+f"(c[1]), "+f"(c[2]), "+f"(c[3])
        : "r"(a[0]), "r"(a[1]), "r"(a[2]), "r"(a[3]), "r"(b0), "r"(b1));
}
__device__ __forceinline__ void ldmx4(uint32_t* r, uint32_t addr) {
    asm volatile("ldmatrix.sync.aligned.m8n8.x4.shared.b16 {%0,%1,%2,%3},[%4];"
                 : "=r"(r[0]), "=r"(r[1]), "=r"(r[2]), "=r"(r[3]) : "r"(addr));
}
__device__ __forceinline__ void ldmx2(uint32_t& r0, uint32_t& r1, uint32_t addr) {
    asm volatile("ldmatrix.sync.aligned.m8n8.x2.shared.b16 {%0,%1},[%2];"
                 : "=r"(r0), "=r"(r1) : "r"(addr));
}
__device__ __forceinline__ void ldmx2t(uint32_t& r0, uint32_t& r1, uint32_t addr) {
    asm volatile("ldmatrix.sync.aligned.m8n8.x2.trans.shared.b16 {%0,%1},[%2];"
                 : "=r"(r0), "=r"(r1) : "r"(addr));
}
__device__ __forceinline__ void cp16(uint32_t saddr, const void* g) {
    asm volatile("cp.async.cg.shared.global [%0], [%1], 16;" :: "r"(saddr), "l"(g));
}
__device__ __forceinline__ void cp_commit() { asm volatile("cp.async.commit_group;"); }
template<int Np> __device__ __forceinline__ void cp_wait() {
    asm volatile("cp.async.wait_group %0;" :: "n"(Np));
}

// ---------------------------------------------------------------------------
// Prep: fused fp32 -> fp16 conversion of x, w_attn, w_proj (one launch)
// ---------------------------------------------------------------------------
#define N4_X  (BT*CDIM/4)
#define N4_WA (CDIM*QKV_N/4)
#define N4_WP (CDIM*CDIM/4)
#define N4_TOT (N4_X + N4_WA + N4_WP)

__global__ __launch_bounds__(256) void conv_all(
    const float4* __restrict__ x, const float4* __restrict__ wa,
    const float4* __restrict__ wp,
    __half2* __restrict__ xh, __half2* __restrict__ wah,
    __half2* __restrict__ wph)
{
    int i = blockIdx.x * 256 + threadIdx.x;
    if (i >= N4_TOT) return;
    const float4* src;
    __half2* dst;
    int j;
    if (i < N4_X)               { src = x;  dst = xh;  j = i; }
    else if (i < N4_X + N4_WA)  { src = wa; dst = wah; j = i - N4_X; }
    else                        { src = wp; dst = wph; j = i - N4_X - N4_WA; }
    float4 v = src[j];
    dst[j * 2]     = __floats2half2_rn(v.x, v.y);
    dst[j * 2 + 1] = __floats2half2_rn(v.z, v.w);
}

// ---------------------------------------------------------------------------
// fp16 GEMM (round-11 proven config): C[M,N] = A[M,K] @ B[K,N].
// 128x128 tile, BK=32, 8 warps (warp tile 64x32), double-buffered cp.async,
// XOR-swizzled smem. EPI=0: fp32 C. EPI=1: QKV scatter as fp16 q/k/v.
// ---------------------------------------------------------------------------
#define SB_BYTES 16384u   // Ah(8K) | Bh(8K)
#define GEMM_SMEM (2 * SB_BYTES)

template<int EPI>
__global__ __launch_bounds__(256)
void gemm_f16(const __half* __restrict__ Ah, const __half* __restrict__ Bh,
              float* __restrict__ C, int N, int K)
{
    extern __shared__ char smem[];
    const uint32_t sbase = smem_u32(smem);

    const int t = threadIdx.x, lane = t & 31, w = t >> 5;
    const int m0 = blockIdx.y * 128, n0 = blockIdx.x * 128;
    const int wm = w & 1, wn = w >> 1;

    float acc[4][4][4] = {};
    const int NIT = K / 32;

    auto load_stage = [&](int it, int buf) {
        uint32_t sb = sbase + buf * SB_BYTES;
        int k0 = it * 32;
        #pragma unroll
        for (int u = 0; u < 2; ++u) {
            int q = t + u * 256;
            int r = q >> 2, c16 = q & 3;
            uint32_t sc = (uint32_t)(r * 4 + (c16 ^ ((r >> 1) & 3))) * 16;
            cp16(sb + sc, Ah + (size_t)(m0 + r) * K + k0 + c16 * 8);
        }
        #pragma unroll
        for (int u = 0; u < 2; ++u) {
            int q = t + u * 256;
            int k = q >> 4, c16 = q & 15;
            uint32_t sc = (uint32_t)(k * 16 + (c16 ^ (k & 7))) * 16;
            cp16(sb + 8192 + sc, Bh + (size_t)(k0 + k) * N + n0 + c16 * 8);
        }
    };

    load_stage(0, 0);
    cp_commit();

    for (int it = 0; it < NIT; ++it) {
        if (it + 1 < NIT) {
            load_stage(it + 1, (it + 1) & 1);
            cp_commit();
            cp_wait<1>();
        } else {
            cp_wait<0>();
        }
        __syncthreads();

        uint32_t sb  = sbase + (it & 1) * SB_BYTES;
        uint32_t sAh = sb, sBh = sb + 8192;

        #pragma unroll
        for (int kk = 0; kk < 2; ++kk) {
            uint32_t ar[4][4], bf[4][2];
            #pragma unroll
            for (int mt = 0; mt < 4; ++mt) {
                int r = wm * 64 + mt * 16 + (lane & 15);
                int c16 = kk * 2 + (lane >> 4);
                uint32_t off = (uint32_t)(r * 4 + (c16 ^ ((r >> 1) & 3))) * 16;
                ldmx4(ar[mt], sAh + off);
            }
            #pragma unroll
            for (int nt = 0; nt < 4; ++nt) {
                int k = kk * 16 + (lane & 15);
                int c16 = wn * 4 + nt;
                uint32_t off = (uint32_t)(k * 16 + (c16 ^ (k & 7))) * 16;
                ldmx2t(bf[nt][0], bf[nt][1], sBh + off);
            }
            #pragma unroll
            for (int mt = 0; mt < 4; ++mt)
                #pragma unroll
                for (int nt = 0; nt < 4; ++nt)
                    mma16816(acc[mt][nt], ar[mt], bf[nt][0], bf[nt][1]);
        }
        __syncthreads();
    }

    // epilogue
    int g = lane >> 2, qoff = (lane & 3) * 2;
    if (EPI == 0) {
        #pragma unroll
        for (int mt = 0; mt < 4; ++mt) {
            int r0 = m0 + wm * 64 + mt * 16 + g;
            #pragma unroll
            for (int nt = 0; nt < 4; ++nt) {
                int n = n0 + wn * 32 + nt * 8 + qoff;
                *(float2*)(C + (size_t)r0 * N + n) =
                    make_float2(acc[mt][nt][0], acc[mt][nt][1]);
                *(float2*)(C + (size_t)(r0 + 8) * N + n) =
                    make_float2(acc[mt][nt][2], acc[mt][nt][3]);
            }
        }
    } else {
        int n_first = n0 + wn * 32;
        int region = n_first >> 10;
        int h = (n_first & 1023) >> 6;
        int dbase = n_first & 63;                 // 0 or 32
        __half* dst = (region == 0) ? g_q : (region == 1) ? g_k : g_v;
        #pragma unroll
        for (int mt = 0; mt < 4; ++mt) {
            int r = m0 + wm * 64 + mt * 16 + g;
            int b = r >> 11, tt = r & 2047;
            size_t base = ((size_t)(b * NHEAD + h) * SEQ + tt) * HDIM;
            #pragma unroll
            for (int nt = 0; nt < 4; ++nt) {
                int d = dbase + nt * 8 + qoff;
                *(__half2*)(dst + base + d) =
                    __floats2half2_rn(acc[mt][nt][0], acc[mt][nt][1]);
                *(__half2*)(dst + base + 8 * HDIM + d) =
                    __floats2half2_rn(acc[mt][nt][2], acc[mt][nt][3]);
            }
        }
    }
}

// ---------------------------------------------------------------------------
// Flash attention, single-pass fp16. KV staged in 128-key smem tiles
// (double buffered), processed as 2x64-key chunks per barrier pair.
// Heavy CTAs first. Writes y as fp16.
// ---------------------------------------------------------------------------
#define LDK 72                   // padded smem row (fp16 elems)
#define ABUF 9216                // bytes per 64xLDK fp16 array
#define KVTILE (4*ABUF)          // kh(2x64) | vh(2x64) = 36864 B per 128 keys
#define ATTN_SMEM (2 * KVTILE)   // 73728 B dynamic

__global__ __launch_bounds__(256) void flash_attn_mma()
{
    extern __shared__ char sm[];
    const uint32_t smb = smem_u32(sm);

    int t = threadIdx.x, lane = t & 31, w = t >> 5;
    int bx = (gridDim.x - 1) - blockIdx.x;        // heavy blocks first
    int bh2 = blockIdx.y;
    int b = bh2 >> 4, h = bh2 & 15;

    size_t headoff = (size_t)bh2 * SEQ * HDIM;

    // ---- stage Q tile (128x64)
    {
        const __half* qg = g_q + headoff + (size_t)bx * 128 * HDIM;
        #pragma unroll
        for (int i = 0; i < 4; ++i) {
            int q = t + i * 256;
            int r = q >> 3, c8 = q & 7;
            uint32_t soff = (uint32_t)(r * LDK + c8 * 8) * 2;
            cp16(smb + soff, qg + r * 64 + c8 * 8);
        }
    }
    cp_commit();
    cp_wait<0>();
    __syncthreads();

    uint32_t qf[4][4];
    {
        int row = w * 16 + (lane & 15);
        #pragma unroll
        for (int kt = 0; kt < 4; ++kt) {
            int col = kt * 16 + (lane >> 4) * 8;
            ldmx4(qf[kt], smb + (uint32_t)(row * LDK + col) * 2);
        }
    }
    __syncthreads();

    float oacc[8][4];
    #pragma unroll
    for (int i = 0; i < 8; ++i) { oacc[i][0]=0.f; oacc[i][1]=0.f; oacc[i][2]=0.f; oacc[i][3]=0.f; }

    float m0 = -1e30f, m1 = -1e30f, l0 = 0.f, l1 = 0.f;
    int g    = lane >> 2;
    int qoff = (lane & 3) * 2;
    int rw   = bx * 128 + w * 16;
    const float scale = 0.125f;

    // KV tile layout: [kh chunk0 | kh chunk1 | vh chunk0 | vh chunk1]
    auto load_kv = [&](int bt, int buf) {            // bt = 128-key tile index
        size_t tb = headoff + (size_t)bt * 128 * HDIM;
        uint32_t bb = smb + buf * KVTILE;
        #pragma unroll
        for (int i = 0; i < 4; ++i) {                // 128 rows x 8 chunks
            int q = t + i * 256;
            int r = q >> 3, c8 = q & 7;              // r in [0,128)
            int ch = r >> 6, rr = r & 63;            // chunk, row-in-chunk
            uint32_t soff = (uint32_t)(ch * ABUF) + (uint32_t)(rr * LDK + c8 * 8) * 2;
            size_t go = tb + (size_t)r * 64 + c8 * 8;
            cp16(bb + soff,            g_k + go);
            cp16(bb + 2 * ABUF + soff, g_v + go);
        }
    };

    int nbt = bx + 1;            // 128-key tiles covering [0, bx*128+128)
    load_kv(0, 0);
    cp_commit();

    for (int bt = 0; bt < nbt; ++bt) {
        if (bt + 1 < nbt) {
            load_kv(bt + 1, (bt + 1) & 1);
            cp_commit();
            cp_wait<1>();
        } else {
            cp_wait<0>();
        }
        __syncthreads();

        uint32_t tilebase = smb + (bt & 1) * KVTILE;

        #pragma unroll
        for (int ch = 0; ch < 2; ++ch) {             // two 64-key chunks
            int kb = bt * 128 + ch * 64;             // chunk key base
            if (kb > rw + 15) break;                 // causal: nothing visible
            uint32_t bb = tilebase + ch * ABUF;      // kh chunk
            uint32_t vb = tilebase + 2 * ABUF + ch * ABUF;  // vh chunk

            // ---- S = Q K^T
            float sacc[8][4];
            #pragma unroll
            for (int i = 0; i < 8; ++i) { sacc[i][0]=0.f; sacc[i][1]=0.f; sacc[i][2]=0.f; sacc[i][3]=0.f; }

            #pragma unroll
            for (int c = 0; c < 4; ++c) {
                int col = c * 16 + (((lane & 15) >> 3)) * 8;
                int keyrb = lane & 7;
                uint32_t kf[8][2];
                #pragma unroll
                for (int nt = 0; nt < 8; ++nt)
                    ldmx2(kf[nt][0], kf[nt][1],
                          bb + (uint32_t)((nt * 8 + keyrb) * LDK + col) * 2);
                #pragma unroll
                for (int nt = 0; nt < 8; ++nt)
                    mma16816(sacc[nt], qf[c], kf[nt][0], kf[nt][1]);
            }

            // ---- scale + causal mask + row max
            int i0 = rw + g, i1 = rw + g + 8;
            float mt0 = -1e30f, mt1 = -1e30f;
            #pragma unroll
            for (int nt = 0; nt < 8; ++nt) {
                int j0 = kb + nt * 8 + qoff;
                float s0 = sacc[nt][0] * scale;
                float s1 = sacc[nt][1] * scale;
                float s2 = sacc[nt][2] * scale;
                float s3 = sacc[nt][3] * scale;
                if (j0     > i0) s0 = -1e30f;
                if (j0 + 1 > i0) s1 = -1e30f;
                if (j0     > i1) s2 = -1e30f;
                if (j0 + 1 > i1) s3 = -1e30f;
                sacc[nt][0] = s0; sacc[nt][1] = s1;
                sacc[nt][2] = s2; sacc[nt][3] = s3;
                mt0 = fmaxf(mt0, fmaxf(s0, s1));
                mt1 = fmaxf(mt1, fmaxf(s2, s3));
            }
            mt0 = fmaxf(mt0, __shfl_xor_sync(0xffffffffu, mt0, 1));
            mt0 = fmaxf(mt0, __shfl_xor_sync(0xffffffffu, mt0, 2));
            mt1 = fmaxf(mt1, __shfl_xor_sync(0xffffffffu, mt1, 1));
            mt1 = fmaxf(mt1, __shfl_xor_sync(0xffffffffu, mt1, 2));

            float mn0 = fmaxf(m0, mt0), mn1 = fmaxf(m1, mt1);
            float a0 = __expf(m0 - mn0), a1 = __expf(m1 - mn1);
            m0 = mn0; m1 = mn1;
            l0 *= a0;  l1 *= a1;
            #pragma unroll
            for (int nt = 0; nt < 8; ++nt) {
                oacc[nt][0] *= a0; oacc[nt][1] *= a0;
                oacc[nt][2] *= a1; oacc[nt][3] *= a1;
            }

            // ---- P = exp(S - m), O += P V
            #pragma unroll
            for (int c2 = 0; c2 < 4; ++c2) {
                float p0 = __expf(sacc[2*c2  ][0] - m0);
                float p1 = __expf(sacc[2*c2  ][1] - m0);
                float p2 = __expf(sacc[2*c2  ][2] - m1);
                float p3 = __expf(sacc[2*c2  ][3] - m1);
                float p4 = __expf(sacc[2*c2+1][0] - m0);
                float p5 = __expf(sacc[2*c2+1][1] - m0);
                float p6 = __expf(sacc[2*c2+1][2] - m1);
                float p7 = __expf(sacc[2*c2+1][3] - m1);
                l0 += p0 + p1 + p4 + p5;
                l1 += p2 + p3 + p6 + p7;

                uint32_t pr[4];
                {
                    __half2 hp;
                    hp = __floats2half2_rn(p0, p1); pr[0] = *(uint32_t*)&hp;
                    hp = __floats2half2_rn(p2, p3); pr[1] = *(uint32_t*)&hp;
                    hp = __floats2half2_rn(p4, p5); pr[2] = *(uint32_t*)&hp;
                    hp = __floats2half2_rn(p6, p7); pr[3] = *(uint32_t*)&hp;
                }

                int keyr = c2 * 16 + (lane & 15);
                uint32_t vf[8][2];
                #pragma unroll
                for (int nt = 0; nt < 8; ++nt)
                    ldmx2t(vf[nt][0], vf[nt][1],
                           vb + (uint32_t)(keyr * LDK + nt * 8) * 2);
                #pragma unroll
                for (int nt = 0; nt < 8; ++nt)
                    mma16816(oacc[nt], pr, vf[nt][0], vf[nt][1]);
            }
        }
        __syncthreads();
    }

    // ---- finalize: write y as fp16
    l0 += __shfl_xor_sync(0xffffffffu, l0, 1);
    l0 += __shfl_xor_sync(0xffffffffu, l0, 2);
    l1 += __shfl_xor_sync(0xffffffffu, l1, 1);
    l1 += __shfl_xor_sync(0xffffffffu, l1, 2);
    float inv0 = 1.f / l0, inv1 = 1.f / l1;

    size_t o0 = ((size_t)(b * SEQ + rw + g    )) * CDIM + h * 64;
    size_t o1 = ((size_t)(b * SEQ + rw + g + 8)) * CDIM + h * 64;
    #pragma unroll
    for (int nt = 0; nt < 8; ++nt) {
        *(__half2*)(g_yh + o0 + nt * 8 + qoff) =
            __floats2half2_rn(oacc[nt][0] * inv0, oacc[nt][1] * inv0);
        *(__half2*)(g_yh + o1 + nt * 8 + qoff) =
            __floats2half2_rn(oacc[nt][2] * inv1, oacc[nt][3] * inv1);
    }
}

// ---------------------------------------------------------------------------
// Launch: fused prep -> QKV GEMM -> attention -> proj GEMM
// ---------------------------------------------------------------------------
extern "C" void kernel_launch(void* const* d_in, const int* in_sizes, int n_in,
                              void* d_out, int out_size)
{
    const float* x      = (const float*)d_in[0];
    const float* w_attn = (const float*)d_in[1];
    const float* w_proj = (const float*)d_in[2];
    float* out = (float*)d_out;

    __half *xh, *yh, *wah, *wph;
    cudaGetSymbolAddress((void**)&xh,  g_xh);
    cudaGetSymbolAddress((void**)&yh,  g_yh);
    cudaGetSymbolAddress((void**)&wah, g_wah);
    cudaGetSymbolAddress((void**)&wph, g_wph);

    cudaFuncSetAttribute((const void*)gemm_f16<0>,
                         cudaFuncAttributeMaxDynamicSharedMemorySize, GEMM_SMEM);
    cudaFuncSetAttribute((const void*)gemm_f16<1>,
                         cudaFuncAttributeMaxDynamicSharedMemorySize, GEMM_SMEM);
    cudaFuncSetAttribute((const void*)flash_attn_mma,
                         cudaFuncAttributeMaxDynamicSharedMemorySize, ATTN_SMEM);

    // fused fp16 conversion (x, w_attn, w_proj in one launch)
    conv_all<<<(N4_TOT + 255) / 256, 256>>>(
        (const float4*)x, (const float4*)w_attn, (const float4*)w_proj,
        (__half2*)xh, (__half2*)wah, (__half2*)wph);

    // 1) QKV GEMM: [8192,1024]@[1024,3072] -> fp16 q/k/v
    {
        dim3 grid(QKV_N / 128, BT / 128);   // 24 x 64
        gemm_f16<1><<<grid, 256, GEMM_SMEM>>>(xh, wah, nullptr, QKV_N, CDIM);
    }
    // 2) attention (single-pass fp16, 128-key tiles, heavy CTAs first)
    {
        dim3 grid(SEQ / 128, BATCH * NHEAD);  // 16 x 64
        flash_attn_mma<<<grid, 256, ATTN_SMEM>>>();
    }
    // 3) proj GEMM: [8192,1024]@[1024,1024] -> fp32 out
    {
        dim3 grid(CDIM / 128, BT / 128);    // 8 x 64
        gemm_f16<0><<<grid, 256, GEMM_SMEM>>>(yh, wph, out, CDIM, CDIM);
    }
}

// round 16
// speedup vs baseline: 1.1010x; 1.0346x over previous
#include <cuda_runtime.h>
#include <cuda_fp16.h>
#include <cstddef>
#include <cstdint>

// Problem constants
#define BATCH 4
#define SEQ   2048
#define CDIM  1024
#define NHEAD 16
#define HDIM  64
#define BT    (BATCH*SEQ)       // 8192
#define QKV_N (3*CDIM)          // 3072

// Scratch (device globals; no allocation allowed)
__device__ alignas(16) __half g_q[BATCH*NHEAD*SEQ*HDIM];       // fp16
__device__ alignas(16) __half g_k[BATCH*NHEAD*SEQ*HDIM];
__device__ alignas(16) __half g_v[BATCH*NHEAD*SEQ*HDIM];
__device__ alignas(16) __half g_xh[BT*CDIM];                   // x fp16 [M,K]
__device__ alignas(16) __half g_yh[BT*CDIM];                   // y fp16 [M,K]
__device__ alignas(16) __half g_wah[CDIM*QKV_N];               // w_attn fp16 [K,N]
__device__ alignas(16) __half g_wph[CDIM*CDIM];                // w_proj fp16 [K,N]

// ---------------------------------------------------------------------------
// Helpers
// ---------------------------------------------------------------------------
__device__ __forceinline__ uint32_t smem_u32(const void* p) {
    return (uint32_t)__cvta_generic_to_shared(p);
}
__device__ __forceinline__ float ex2f(float x) {
    float r;
    asm("ex2.approx.f32 %0, %1;" : "=f"(r) : "f"(x));
    return r;
}
__device__ __forceinline__ void mma16816(float* c, const uint32_t* a,
                                         uint32_t b0, uint32_t b1) {
    asm volatile(
        "mma.sync.aligned.m16n8k16.row.col.f32.f16.f16.f32 "
        "{%0,%1,%2,%3},{%4,%5,%6,%7},{%8,%9},{%0,%1,%2,%3};"
        : "+f"(c[0]), "+f"(c[1]), "+f"(c[2]), "+f"(c[3])
        : "r"(a[0]), "r"(a[1]), "r"(a[2]), "r"(a[3]), "r"(b0), "r"(b1));
}
__device__ __forceinline__ void ldmx4(uint32_t* r, uint32_t addr) {
    asm volatile("ldmatrix.sync.aligned.m8n8.x4.shared.b16 {%0,%1,%2,%3},[%4];"
                 : "=r"(r[0]), "=r"(r[1]), "=r"(r[2]), "=r"(r[3]) : "r"(addr));
}
__device__ __forceinline__ void ldmx2(uint32_t& r0, uint32_t& r1, uint32_t addr) {
    asm volatile("ldmatrix.sync.aligned.m8n8.x2.shared.b16 {%0,%1},[%2];"
                 : "=r"(r0), "=r"(r1) : "r"(addr));
}
__device__ __forceinline__ void ldmx2t(uint32_t& r0, uint32_t& r1, uint32_t addr) {
    asm volatile("ldmatrix.sync.aligned.m8n8.x2.trans.shared.b16 {%0,%1},[%2];"
                 : "=r"(r0), "=r"(r1) : "r"(addr));
}
__device__ __forceinline__ void cp16(uint32_t saddr, const void* g) {
    asm volatile("cp.async.cg.shared.global [%0], [%1], 16;" :: "r"(saddr), "l"(g));
}
__device__ __forceinline__ void cp_commit() { asm volatile("cp.async.commit_group;"); }
template<int Np> __device__ __forceinline__ void cp_wait() {
    asm volatile("cp.async.wait_group %0;" :: "n"(Np));
}

// ---------------------------------------------------------------------------
// Prep: fused fp32 -> fp16 conversion of x, w_attn, w_proj (one launch)
// ---------------------------------------------------------------------------
#define N4_X  (BT*CDIM/4)
#define N4_WA (CDIM*QKV_N/4)
#define N4_WP (CDIM*CDIM/4)
#define N4_TOT (N4_X + N4_WA + N4_WP)

__global__ __launch_bounds__(256) void conv_all(
    const float4* __restrict__ x, const float4* __restrict__ wa,
    const float4* __restrict__ wp,
    __half2* __restrict__ xh, __half2* __restrict__ wah,
    __half2* __restrict__ wph)
{
    int i = blockIdx.x * 256 + threadIdx.x;
    if (i >= N4_TOT) return;
    const float4* src;
    __half2* dst;
    int j;
    if (i < N4_X)               { src = x;  dst = xh;  j = i; }
    else if (i < N4_X + N4_WA)  { src = wa; dst = wah; j = i - N4_X; }
    else                        { src = wp; dst = wph; j = i - N4_X - N4_WA; }
    float4 v = src[j];
    dst[j * 2]     = __floats2half2_rn(v.x, v.y);
    dst[j * 2 + 1] = __floats2half2_rn(v.z, v.w);
}

// ---------------------------------------------------------------------------
// fp16 GEMM (proven config): C[M,N] = A[M,K] @ B[K,N].
// 128x128 tile, BK=32, 8 warps (warp tile 64x32), double-buffered cp.async,
// XOR-swizzled smem. EPI=0: fp32 C. EPI=1: QKV scatter as fp16 q/k/v.
// ---------------------------------------------------------------------------
#define SB_BYTES 16384u   // Ah(8K) | Bh(8K)
#define GEMM_SMEM (2 * SB_BYTES)

template<int EPI>
__global__ __launch_bounds__(256)
void gemm_f16(const __half* __restrict__ Ah, const __half* __restrict__ Bh,
              float* __restrict__ C, int N, int K)
{
    extern __shared__ char smem[];
    const uint32_t sbase = smem_u32(smem);

    const int t = threadIdx.x, lane = t & 31, w = t >> 5;
    const int m0 = blockIdx.y * 128, n0 = blockIdx.x * 128;
    const int wm = w & 1, wn = w >> 1;

    float acc[4][4][4] = {};
    const int NIT = K / 32;

    auto load_stage = [&](int it, int buf) {
        uint32_t sb = sbase + buf * SB_BYTES;
        int k0 = it * 32;
        #pragma unroll
        for (int u = 0; u < 2; ++u) {
            int q = t + u * 256;
            int r = q >> 2, c16 = q & 3;
            uint32_t sc = (uint32_t)(r * 4 + (c16 ^ ((r >> 1) & 3))) * 16;
            cp16(sb + sc, Ah + (size_t)(m0 + r) * K + k0 + c16 * 8);
        }
        #pragma unroll
        for (int u = 0; u < 2; ++u) {
            int q = t + u * 256;
            int k = q >> 4, c16 = q & 15;
            uint32_t sc = (uint32_t)(k * 16 + (c16 ^ (k & 7))) * 16;
            cp16(sb + 8192 + sc, Bh + (size_t)(k0 + k) * N + n0 + c16 * 8);
        }
    };

    load_stage(0, 0);
    cp_commit();

    for (int it = 0; it < NIT; ++it) {
        if (it + 1 < NIT) {
            load_stage(it + 1, (it + 1) & 1);
            cp_commit();
            cp_wait<1>();
        } else {
            cp_wait<0>();
        }
        __syncthreads();

        uint32_t sb  = sbase + (it & 1) * SB_BYTES;
        uint32_t sAh = sb, sBh = sb + 8192;

        #pragma unroll
        for (int kk = 0; kk < 2; ++kk) {
            uint32_t ar[4][4], bf[4][2];
            #pragma unroll
            for (int mt = 0; mt < 4; ++mt) {
                int r = wm * 64 + mt * 16 + (lane & 15);
                int c16 = kk * 2 + (lane >> 4);
                uint32_t off = (uint32_t)(r * 4 + (c16 ^ ((r >> 1) & 3))) * 16;
                ldmx4(ar[mt], sAh + off);
            }
            #pragma unroll
            for (int nt = 0; nt < 4; ++nt) {
                int k = kk * 16 + (lane & 15);
                int c16 = wn * 4 + nt;
                uint32_t off = (uint32_t)(k * 16 + (c16 ^ (k & 7))) * 16;
                ldmx2t(bf[nt][0], bf[nt][1], sBh + off);
            }
            #pragma unroll
            for (int mt = 0; mt < 4; ++mt)
                #pragma unroll
                for (int nt = 0; nt < 4; ++nt)
                    mma16816(acc[mt][nt], ar[mt], bf[nt][0], bf[nt][1]);
        }
        __syncthreads();
    }

    // epilogue
    int g = lane >> 2, qoff = (lane & 3) * 2;
    if (EPI == 0) {
        #pragma unroll
        for (int mt = 0; mt < 4; ++mt) {
            int r0 = m0 + wm * 64 + mt * 16 + g;
            #pragma unroll
            for (int nt = 0; nt < 4; ++nt) {
                int n = n0 + wn * 32 + nt * 8 + qoff;
                *(float2*)(C + (size_t)r0 * N + n) =
                    make_float2(acc[mt][nt][0], acc[mt][nt][1]);
                *(float2*)(C + (size_t)(r0 + 8) * N + n) =
                    make_float2(acc[mt][nt][2], acc[mt][nt][3]);
            }
        }
    } else {
        int n_first = n0 + wn * 32;
        int region = n_first >> 10;
        int h = (n_first & 1023) >> 6;
        int dbase = n_first & 63;                 // 0 or 32
        __half* dst = (region == 0) ? g_q : (region == 1) ? g_k : g_v;
        #pragma unroll
        for (int mt = 0; mt < 4; ++mt) {
            int r = m0 + wm * 64 + mt * 16 + g;
            int b = r >> 11, tt = r & 2047;
            size_t base = ((size_t)(b * NHEAD + h) * SEQ + tt) * HDIM;
            #pragma unroll
            for (int nt = 0; nt < 4; ++nt) {
                int d = dbase + nt * 8 + qoff;
                *(__half2*)(dst + base + d) =
                    __floats2half2_rn(acc[mt][nt][0], acc[mt][nt][1]);
                *(__half2*)(dst + base + 8 * HDIM + d) =
                    __floats2half2_rn(acc[mt][nt][2], acc[mt][nt][3]);
            }
        }
    }
}

// ---------------------------------------------------------------------------
// Flash attention, single-pass fp16, log2-domain softmax (ex2.approx),
// full-visibility fast path. 128-key KV tiles (double buffered), 2x64 chunks.
// Heavy CTAs first. Writes y as fp16.
// ---------------------------------------------------------------------------
#define LDK 72                   // padded smem row (fp16 elems)
#define ABUF 9216                // bytes per 64xLDK fp16 array
#define KVTILE (4*ABUF)          // kh(2x64) | vh(2x64) = 36864 B per 128 keys
#define ATTN_SMEM (2 * KVTILE)   // 73728 B dynamic

__global__ __launch_bounds__(256) void flash_attn_mma()
{
    extern __shared__ char sm[];
    const uint32_t smb = smem_u32(sm);

    int t = threadIdx.x, lane = t & 31, w = t >> 5;
    int bx = (gridDim.x - 1) - blockIdx.x;        // heavy blocks first
    int bh2 = blockIdx.y;
    int b = bh2 >> 4, h = bh2 & 15;

    size_t headoff = (size_t)bh2 * SEQ * HDIM;

    // ---- stage Q tile (128x64)
    {
        const __half* qg = g_q + headoff + (size_t)bx * 128 * HDIM;
        #pragma unroll
        for (int i = 0; i < 4; ++i) {
            int q = t + i * 256;
            int r = q >> 3, c8 = q & 7;
            uint32_t soff = (uint32_t)(r * LDK + c8 * 8) * 2;
            cp16(smb + soff, qg + r * 64 + c8 * 8);
        }
    }
    cp_commit();
    cp_wait<0>();
    __syncthreads();

    uint32_t qf[4][4];
    {
        int row = w * 16 + (lane & 15);
        #pragma unroll
        for (int kt = 0; kt < 4; ++kt) {
            int col = kt * 16 + (lane >> 4) * 8;
            ldmx4(qf[kt], smb + (uint32_t)(row * LDK + col) * 2);
        }
    }
    __syncthreads();

    float oacc[8][4];
    #pragma unroll
    for (int i = 0; i < 8; ++i) { oacc[i][0]=0.f; oacc[i][1]=0.f; oacc[i][2]=0.f; oacc[i][3]=0.f; }

    // log2-domain: s' = s * (scale*log2e); p = 2^(s'-m')
    const float scale2 = 0.125f * 1.44269504088896340736f;
    float m0 = -1e30f, m1 = -1e30f, l0 = 0.f, l1 = 0.f;
    int g    = lane >> 2;
    int qoff = (lane & 3) * 2;
    int rw   = bx * 128 + w * 16;

    // KV tile layout: [kh chunk0 | kh chunk1 | vh chunk0 | vh chunk1]
    auto load_kv = [&](int bt, int buf) {
        size_t tb = headoff + (size_t)bt * 128 * HDIM;
        uint32_t bb = smb + buf * KVTILE;
        #pragma unroll
        for (int i = 0; i < 4; ++i) {
            int q = t + i * 256;
            int r = q >> 3, c8 = q & 7;
            int ch = r >> 6, rr = r & 63;
            uint32_t soff = (uint32_t)(ch * ABUF) + (uint32_t)(rr * LDK + c8 * 8) * 2;
            size_t go = tb + (size_t)r * 64 + c8 * 8;
            cp16(bb + soff,            g_k + go);
            cp16(bb + 2 * ABUF + soff, g_v + go);
        }
    };

    int nbt = bx + 1;
    load_kv(0, 0);
    cp_commit();

    for (int bt = 0; bt < nbt; ++bt) {
        if (bt + 1 < nbt) {
            load_kv(bt + 1, (bt + 1) & 1);
            cp_commit();
            cp_wait<1>();
        } else {
            cp_wait<0>();
        }
        __syncthreads();

        uint32_t tilebase = smb + (bt & 1) * KVTILE;

        #pragma unroll
        for (int ch = 0; ch < 2; ++ch) {
            int kb = bt * 128 + ch * 64;
            if (kb > rw + 15) break;
            uint32_t bb = tilebase + ch * ABUF;
            uint32_t vb = tilebase + 2 * ABUF + ch * ABUF;

            // ---- S = Q K^T
            float sacc[8][4];
            #pragma unroll
            for (int i = 0; i < 8; ++i) { sacc[i][0]=0.f; sacc[i][1]=0.f; sacc[i][2]=0.f; sacc[i][3]=0.f; }

            #pragma unroll
            for (int c = 0; c < 4; ++c) {
                int col = c * 16 + (((lane & 15) >> 3)) * 8;
                int keyrb = lane & 7;
                uint32_t kf[8][2];
                #pragma unroll
                for (int nt = 0; nt < 8; ++nt)
                    ldmx2(kf[nt][0], kf[nt][1],
                          bb + (uint32_t)((nt * 8 + keyrb) * LDK + col) * 2);
                #pragma unroll
                for (int nt = 0; nt < 8; ++nt)
                    mma16816(sacc[nt], qf[c], kf[nt][0], kf[nt][1]);
            }

            // ---- scale (log2 domain) + causal mask + row max
            int i0 = rw + g, i1 = rw + g + 8;
            float mt0 = -1e30f, mt1 = -1e30f;
            if (kb + 63 <= rw) {
                // fully visible: no masking needed
                #pragma unroll
                for (int nt = 0; nt < 8; ++nt) {
                    float s0 = sacc[nt][0] * scale2;
                    float s1 = sacc[nt][1] * scale2;
                    float s2 = sacc[nt][2] * scale2;
                    float s3 = sacc[nt][3] * scale2;
                    sacc[nt][0] = s0; sacc[nt][1] = s1;
                    sacc[nt][2] = s2; sacc[nt][3] = s3;
                    mt0 = fmaxf(mt0, fmaxf(s0, s1));
                    mt1 = fmaxf(mt1, fmaxf(s2, s3));
                }
            } else {
                #pragma unroll
                for (int nt = 0; nt < 8; ++nt) {
                    int j0 = kb + nt * 8 + qoff;
                    float s0 = sacc[nt][0] * scale2;
                    float s1 = sacc[nt][1] * scale2;
                    float s2 = sacc[nt][2] * scale2;
                    float s3 = sacc[nt][3] * scale2;
                    if (j0     > i0) s0 = -1e30f;
                    if (j0 + 1 > i0) s1 = -1e30f;
                    if (j0     > i1) s2 = -1e30f;
                    if (j0 + 1 > i1) s3 = -1e30f;
                    sacc[nt][0] = s0; sacc[nt][1] = s1;
                    sacc[nt][2] = s2; sacc[nt][3] = s3;
                    mt0 = fmaxf(mt0, fmaxf(s0, s1));
                    mt1 = fmaxf(mt1, fmaxf(s2, s3));
                }
            }
            mt0 = fmaxf(mt0, __shfl_xor_sync(0xffffffffu, mt0, 1));
            mt0 = fmaxf(mt0, __shfl_xor_sync(0xffffffffu, mt0, 2));
            mt1 = fmaxf(mt1, __shfl_xor_sync(0xffffffffu, mt1, 1));
            mt1 = fmaxf(mt1, __shfl_xor_sync(0xffffffffu, mt1, 2));

            float mn0 = fmaxf(m0, mt0), mn1 = fmaxf(m1, mt1);
            float a0 = ex2f(m0 - mn0), a1 = ex2f(m1 - mn1);
            m0 = mn0; m1 = mn1;
            l0 *= a0;  l1 *= a1;
            #pragma unroll
            for (int nt = 0; nt < 8; ++nt) {
                oacc[nt][0] *= a0; oacc[nt][1] *= a0;
                oacc[nt][2] *= a1; oacc[nt][3] *= a1;
            }

            // ---- P = 2^(S' - m'), O += P V
            #pragma unroll
            for (int c2 = 0; c2 < 4; ++c2) {
                float p0 = ex2f(sacc[2*c2  ][0] - m0);
                float p1 = ex2f(sacc[2*c2  ][1] - m0);
                float p2 = ex2f(sacc[2*c2  ][2] - m1);
                float p3 = ex2f(sacc[2*c2  ][3] - m1);
                float p4 = ex2f(sacc[2*c2+1][0] - m0);
                float p5 = ex2f(sacc[2*c2+1][1] - m0);
                float p6 = ex2f(sacc[2*c2+1][2] - m1);
                float p7 = ex2f(sacc[2*c2+1][3] - m1);
                l0 += p0 + p1 + p4 + p5;
                l1 += p2 + p3 + p6 + p7;

                uint32_t pr[4];
                {
                    __half2 hp;
                    hp = __floats2half2_rn(p0, p1); pr[0] = *(uint32_t*)&hp;
                    hp = __floats2half2_rn(p2, p3); pr[1] = *(uint32_t*)&hp;
                    hp = __floats2half2_rn(p4, p5); pr[2] = *(uint32_t*)&hp;
                    hp = __floats2half2_rn(p6, p7); pr[3] = *(uint32_t*)&hp;
                }

                int keyr = c2 * 16 + (lane & 15);
                uint32_t vf[8][2];
                #pragma unroll
                for (int nt = 0; nt < 8; ++nt)
                    ldmx2t(vf[nt][0], vf[nt][1],
                           vb + (uint32_t)(keyr * LDK + nt * 8) * 2);
                #pragma unroll
                for (int nt = 0; nt < 8; ++nt)
                    mma16816(oacc[nt], pr, vf[nt][0], vf[nt][1]);
            }
        }
        __syncthreads();
    }

    // ---- finalize: write y as fp16
    l0 += __shfl_xor_sync(0xffffffffu, l0, 1);
    l0 += __shfl_xor_sync(0xffffffffu, l0, 2);
    l1 += __shfl_xor_sync(0xffffffffu, l1, 1);
    l1 += __shfl_xor_sync(0xffffffffu, l1, 2);
    float inv0 = 1.f / l0, inv1 = 1.f / l1;

    size_t o0 = ((size_t)(b * SEQ + rw + g    )) * CDIM + h * 64;
    size_t o1 = ((size_t)(b * SEQ + rw + g + 8)) * CDIM + h * 64;
    #pragma unroll
    for (int nt = 0; nt < 8; ++nt) {
        *(__half2*)(g_yh + o0 + nt * 8 + qoff) =
            __floats2half2_rn(oacc[nt][0] * inv0, oacc[nt][1] * inv0);
        *(__half2*)(g_yh + o1 + nt * 8 + qoff) =
            __floats2half2_rn(oacc[nt][2] * inv1, oacc[nt][3] * inv1);
    }
}

// ---------------------------------------------------------------------------
// Launch: fused prep -> QKV GEMM -> attention -> proj GEMM
// ---------------------------------------------------------------------------
extern "C" void kernel_launch(void* const* d_in, const int* in_sizes, int n_in,
                              void* d_out, int out_size)
{
    const float* x      = (const float*)d_in[0];
    const float* w_attn = (const float*)d_in[1];
    const float* w_proj = (const float*)d_in[2];
    float* out = (float*)d_out;

    __half *xh, *yh, *wah, *wph;
    cudaGetSymbolAddress((void**)&xh,  g_xh);
    cudaGetSymbolAddress((void**)&yh,  g_yh);
    cudaGetSymbolAddress((void**)&wah, g_wah);
    cudaGetSymbolAddress((void**)&wph, g_wph);

    cudaFuncSetAttribute((const void*)gemm_f16<0>,
                         cudaFuncAttributeMaxDynamicSharedMemorySize, GEMM_SMEM);
    cudaFuncSetAttribute((const void*)gemm_f16<1>,
                         cudaFuncAttributeMaxDynamicSharedMemorySize, GEMM_SMEM);
    cudaFuncSetAttribute((const void*)flash_attn_mma,
                         cudaFuncAttributeMaxDynamicSharedMemorySize, ATTN_SMEM);

    // fused fp16 conversion (x, w_attn, w_proj in one launch)
    conv_all<<<(N4_TOT + 255) / 256, 256>>>(
        (const float4*)x, (const float4*)w_attn, (const float4*)w_proj,
        (__half2*)xh, (__half2*)wah, (__half2*)wph);

    // 1) QKV GEMM: [8192,1024]@[1024,3072] -> fp16 q/k/v
    {
        dim3 grid(QKV_N / 128, BT / 128);   // 24 x 64
        gemm_f16<1><<<grid, 256, GEMM_SMEM>>>(xh, wah, nullptr, QKV_N, CDIM);
    }
    // 2) attention (single-pass fp16, log2 softmax, 128-key tiles)
    {
        dim3 grid(SEQ / 128, BATCH * NHEAD);  // 16 x 64
        flash_attn_mma<<<grid, 256, ATTN_SMEM>>>();
    }
    // 3) proj GEMM: [8192,1024]@[1024,1024] -> fp32 out
    {
        dim3 grid(CDIM / 128, BT / 128);    // 8 x 64
        gemm_f16<0><<<grid, 256, GEMM_SMEM>>>(yh, wph, out, CDIM, CDIM);
    }
}